// round 6
// baseline (speedup 1.0000x reference)
#include <cuda_runtime.h>
#include <cuda_bf16.h>
#include <cstdint>

// Shapes: x [4,2048,1024] f32, W [1024,3072] f32, b [3072] f32
// out [4,16,2048,64] f32 = scale * Q (K^T V),  scale = 32
#define M_TOT 8192
#define K_DIM 1024
#define N_TOT 3072
#define BH    64
#define SEQ   2048
#define HD    64
#define NSPLIT 16

// ---- stage-1 geometry ----
#define TBM 256
#define TBN 256
#define CHUNK 64                 // bf16 k-elems per chunk = 128B rows (SW128 atom)
#define NVCHUNK 48               // 16 k-groups x 3 passes (hi.hi, hi.lo, lo.hi)
#define A_TILE 32768             // 256 rows x 128B
#define B_TILE 32768
#define A_RING 3
#define B_RING 4
#define QKV_SMEM (1024 + 1024 + A_RING * A_TILE + B_RING * B_TILE)  // 231424
#define IDESC_BF16 0x08400490u   // F32 acc | aBF16 | bBF16 | N=256 | M=128

// fallback tile params
#define GBK 32
#define APAD 8

// Device-pass feature gate: tcgen05 only on arch-specific ('a') targets.
#if defined(__CUDA_ARCH__) && (defined(__CUDA_ARCH_FEAT_SM103_ALL) || \
    defined(__CUDA_ARCH_FEAT_SM100_ALL) || defined(__CUDA_ARCH_SPECIFIC__))
#define USE_TC 1
#else
#define USE_TC 0
#endif

// Scratch (device globals; no runtime allocation allowed)
__device__ __nv_bfloat16 g_Xh[(size_t)M_TOT * K_DIM];  // 16.8 MB
__device__ __nv_bfloat16 g_Xl[(size_t)M_TOT * K_DIM];  // 16.8 MB
__device__ __nv_bfloat16 g_Wh[(size_t)N_TOT * K_DIM];  // 6.3 MB (transposed)
__device__ __nv_bfloat16 g_Wl[(size_t)N_TOT * K_DIM];  // 6.3 MB
__device__ float g_Q[BH * SEQ * HD];                   // 32 MB
__device__ float g_K[BH * SEQ * HD];                   // 32 MB
__device__ float g_V[BH * SEQ * HD];                   // 32 MB
__device__ float g_KtVp[BH * NSPLIT * HD * HD];        // 16.8 MB
__device__ float g_KtV[BH * HD * HD];                  // 1 MB

// ---------------------------------------------------------------------------
// common helpers
// ---------------------------------------------------------------------------
__device__ __forceinline__ void split2(float a, float b, uint32_t& hi, uint32_t& lo) {
    __nv_bfloat16 ah = __float2bfloat16_rn(a);
    __nv_bfloat16 bh = __float2bfloat16_rn(b);
    __nv_bfloat16 al = __float2bfloat16_rn(a - __bfloat162float(ah));
    __nv_bfloat16 bl = __float2bfloat16_rn(b - __bfloat162float(bh));
    hi = (uint32_t)(*reinterpret_cast<uint16_t*>(&ah)) |
         ((uint32_t)(*reinterpret_cast<uint16_t*>(&bh)) << 16);
    lo = (uint32_t)(*reinterpret_cast<uint16_t*>(&al)) |
         ((uint32_t)(*reinterpret_cast<uint16_t*>(&bl)) << 16);
}

__device__ __forceinline__ void cp16s(uint32_t smem_addr, const void* gmem) {
    asm volatile("cp.async.cg.shared.global [%0], [%1], 16;" :: "r"(smem_addr), "l"(gmem));
}

#if USE_TC
__device__ __forceinline__ uint32_t elect_one_pred() {
    uint32_t pred;
    asm volatile("{\n\t.reg .pred p;\n\telect.sync _|p, 0xFFFFFFFF;\n\t"
                 "selp.b32 %0, 1, 0, p;\n\t}" : "=r"(pred));
    return pred;
}

static constexpr uint64_t DESC_BASE_SW128 =
    (uint64_t(2) << 61) | (uint64_t(1) << 46) | (uint64_t(64) << 32) | (uint64_t(1) << 16);
__device__ __forceinline__ uint64_t make_desc(uint32_t addr) {
    return DESC_BASE_SW128 | ((uint64_t)(addr >> 4) & 0x3FFF);
}

__device__ __forceinline__ void mma_f16_ss(uint32_t d, uint64_t ad, uint64_t bd,
                                           uint32_t idesc, uint32_t en) {
    asm volatile(
        "{\n\t.reg .pred p;\n\tsetp.ne.u32 p, %5, 0;\n\t"
        "tcgen05.mma.cta_group::1.kind::f16 [%0], %1, %2, %3, {%4,%4,%4,%4}, p;\n\t}"
        :: "r"(d), "l"(ad), "l"(bd), "r"(idesc), "r"(0u), "r"(en) : "memory");
}

__device__ __forceinline__ void mbar_init(uint32_t a, uint32_t cnt) {
    asm volatile("mbarrier.init.shared.b64 [%0], %1;" :: "r"(a), "r"(cnt) : "memory");
}
__device__ __forceinline__ void mbar_wait(uint32_t a, uint32_t parity) {
    asm volatile(
        "{\n\t.reg .pred P;\n\tLAB_%=:\n\t"
        "mbarrier.try_wait.parity.acquire.cta.shared::cta.b64 P, [%0], %1;\n\t"
        "@!P bra LAB_%=;\n\t}" :: "r"(a), "r"(parity) : "memory");
}
__device__ __forceinline__ void tc_commit(uint32_t mbar) {
    asm volatile(
        "tcgen05.commit.cta_group::1.mbarrier::arrive::one.shared::cluster.b64 [%0];"
        :: "r"(mbar) : "memory");
}

#define LDTM_X32(r, a)                                                         \
    asm volatile("tcgen05.ld.sync.aligned.32x32b.x32.b32 "                     \
        "{%0,%1,%2,%3,%4,%5,%6,%7,%8,%9,%10,%11,%12,%13,%14,%15,"              \
        "%16,%17,%18,%19,%20,%21,%22,%23,%24,%25,%26,%27,%28,%29,%30,%31},"    \
        "[%32];"                                                               \
        : "=r"((r)[0]),"=r"((r)[1]),"=r"((r)[2]),"=r"((r)[3]),                 \
          "=r"((r)[4]),"=r"((r)[5]),"=r"((r)[6]),"=r"((r)[7]),                 \
          "=r"((r)[8]),"=r"((r)[9]),"=r"((r)[10]),"=r"((r)[11]),               \
          "=r"((r)[12]),"=r"((r)[13]),"=r"((r)[14]),"=r"((r)[15]),             \
          "=r"((r)[16]),"=r"((r)[17]),"=r"((r)[18]),"=r"((r)[19]),             \
          "=r"((r)[20]),"=r"((r)[21]),"=r"((r)[22]),"=r"((r)[23]),             \
          "=r"((r)[24]),"=r"((r)[25]),"=r"((r)[26]),"=r"((r)[27]),             \
          "=r"((r)[28]),"=r"((r)[29]),"=r"((r)[30]),"=r"((r)[31])              \
        : "r"(a))
#else
__device__ __forceinline__ void mma_bf16(float* c, const uint32_t* a, const uint32_t* b) {
    asm volatile(
        "mma.sync.aligned.m16n8k16.row.col.f32.bf16.bf16.f32 "
        "{%0,%1,%2,%3}, {%4,%5,%6,%7}, {%8,%9}, {%0,%1,%2,%3};"
        : "+f"(c[0]), "+f"(c[1]), "+f"(c[2]), "+f"(c[3])
        : "r"(a[0]), "r"(a[1]), "r"(a[2]), "r"(a[3]), "r"(b[0]), "r"(b[1]));
}
__device__ __forceinline__ void ldsm_x4(uint32_t* r, const void* p) {
    uint32_t a = (uint32_t)__cvta_generic_to_shared(p);
    asm volatile("ldmatrix.sync.aligned.m8n8.x4.shared.b16 {%0,%1,%2,%3}, [%4];"
                 : "=r"(r[0]), "=r"(r[1]), "=r"(r[2]), "=r"(r[3]) : "r"(a));
}
#endif

// ---------------------------------------------------------------------------
// Precompute: x [M][K] f32 -> Xh/Xl [M][K] bf16
// ---------------------------------------------------------------------------
__global__ __launch_bounds__(256) void split_x(const float* __restrict__ x) {
    int i = blockIdx.x * 256 + threadIdx.x;
    int m = i >> 8, k4 = (i & 255) << 2;
    float4 v = *(const float4*)&x[(size_t)m * K_DIM + k4];
    uint32_t h01, l01, h23, l23;
    split2(v.x, v.y, h01, l01);
    split2(v.z, v.w, h23, l23);
    size_t base = (size_t)m * K_DIM + k4;
    *(uint2*)&g_Xh[base] = make_uint2(h01, h23);
    *(uint2*)&g_Xl[base] = make_uint2(l01, l23);
}

// ---------------------------------------------------------------------------
// Precompute: W [K][N] f32 -> Wh/Wl [N][K] bf16 (transposed)
// ---------------------------------------------------------------------------
__global__ __launch_bounds__(256) void split_w(const float* __restrict__ W) {
    __shared__ float ts[32][33];
    const int k0 = blockIdx.x * 32, n0 = blockIdx.y * 32;
    const int r = threadIdx.x >> 5, c = threadIdx.x & 31;
#pragma unroll
    for (int i = 0; i < 4; i++)
        ts[r + 8 * i][c] = W[(size_t)(k0 + r + 8 * i) * N_TOT + n0 + c];
    __syncthreads();
#pragma unroll
    for (int i = 0; i < 4; i++) {
        int n = n0 + r + 8 * i;
        float f = ts[c][r + 8 * i];
        __nv_bfloat16 hb = __float2bfloat16_rn(f);
        __nv_bfloat16 lb = __float2bfloat16_rn(f - __bfloat162float(hb));
        size_t base = (size_t)n * K_DIM + k0 + c;
        g_Wh[base] = hb;
        g_Wl[base] = lb;
    }
}

// ---------------------------------------------------------------------------
// Stage 1: qkv = x @ W + b via 3-term bf16 split on tcgen05, dedup tile loads.
// Virtual chunk u = 3j+p over k-group j (64 elems), pass p:
//   p=0: A=Xh_j (load, slot 2j%3), B=Wh_j (load, slot 2j%4)
//   p=1: A=Xh_j (reuse),           B=Wl_j (load, slot (2j+1)%4)
//   p=2: A=Xl_j (load, (2j+1)%3),  B=Wh_j (reuse)
// Slot reuse gated on commit-mbar of chunk u-4 (in-order MMA completion).
// ---------------------------------------------------------------------------
extern __shared__ char dynsmem[];

__global__ __launch_bounds__(256, 1) void qkv_gemm(const float* __restrict__ bias) {
#if USE_TC
    const int tid = threadIdx.x, wid = tid >> 5, lane = tid & 31;
    const int bm = blockIdx.y * TBM, bn = blockIdx.x * TBN;

    uint32_t sb_raw = (uint32_t)__cvta_generic_to_shared(dynsmem);
    uint32_t s0 = (sb_raw + 1023) & ~1023u;
    uint32_t tilesA = s0 + 1024;
    uint32_t tilesB = tilesA + A_RING * A_TILE;

    if (tid == 0) {
        mbar_init(s0 + 8, 1);
        mbar_init(s0 + 16, 1);
        mbar_init(s0 + 24, 1);
        mbar_init(s0 + 32, 1);
    }
    if (wid == 0)
        asm volatile("tcgen05.alloc.cta_group::1.sync.aligned.shared::cta.b32 [%0], %1;"
                     :: "r"(s0), "r"(512u) : "memory");
    __syncthreads();
    uint32_t tmem;
    asm volatile("ld.shared.b32 %0, [%1];" : "=r"(tmem) : "r"(s0));

    auto issue_chunk = [&](int u) {
        const int j = u / 3, p = u - 3 * j;
        const int ja = j * CHUNK;
        if (p != 1) {  // A load (p=0: Xh, p=2: Xl)
            const __nv_bfloat16* ag =
                ((p == 0) ? g_Xh : g_Xl) + (size_t)bm * K_DIM + ja;
            const uint32_t dst = tilesA + ((2 * j + (p == 2 ? 1 : 0)) % A_RING) * A_TILE;
#pragma unroll
            for (int i = 0; i < 8; i++) {
                int idx = tid + i * 256;
                int r = idx >> 3, s = idx & 7;
                cp16s(dst + (r << 7) + ((s ^ (r & 7)) << 4),
                      ag + (size_t)r * K_DIM + s * 8);
            }
        }
        if (p != 2) {  // B load (p=0: Wh, p=1: Wl)
            const __nv_bfloat16* bg =
                ((p == 0) ? g_Wh : g_Wl) + (size_t)bn * K_DIM + ja;
            const uint32_t dst = tilesB + ((2 * j + (p == 1 ? 1 : 0)) % B_RING) * B_TILE;
#pragma unroll
            for (int i = 0; i < 8; i++) {
                int idx = tid + i * 256;
                int r = idx >> 3, s = idx & 7;
                cp16s(dst + (r << 7) + ((s ^ (r & 7)) << 4),
                      bg + (size_t)r * K_DIM + s * 8);
            }
        }
        asm volatile("cp.async.commit_group;" ::: "memory");
    };

    issue_chunk(0);
    issue_chunk(1);

    for (int t = 0; t < NVCHUNK; t++) {
        if (t < NVCHUNK - 1)
            asm volatile("cp.async.wait_group 1;" ::: "memory");
        else
            asm volatile("cp.async.wait_group 0;" ::: "memory");
        __syncthreads();

        if (wid == 0 && elect_one_pred()) {
            asm volatile("fence.proxy.async.shared::cta;" ::: "memory");
            const int j = t / 3, p = t - 3 * j;
            const uint32_t aslot = (2 * j + (p == 2 ? 1 : 0)) % A_RING;
            const uint32_t bslot = (2 * j + (p == 1 ? 1 : 0)) % B_RING;
            const uint32_t ab = tilesA + aslot * A_TILE;
            const uint32_t bb = tilesB + bslot * B_TILE;
            uint64_t a0 = make_desc(ab);
            uint64_t a1 = make_desc(ab + 16384);     // rows 128..255 of A tile
            uint64_t bd = make_desc(bb);
#pragma unroll
            for (int k = 0; k < 4; k++) {
                uint32_t en = (t > 0 || k > 0) ? 1u : 0u;
                mma_f16_ss(tmem,       a0 + k * 2, bd + k * 2, IDESC_BF16, en);
                mma_f16_ss(tmem + 256, a1 + k * 2, bd + k * 2, IDESC_BF16, en);
            }
            tc_commit(s0 + 8 + 8 * (t % 3));
        }

        const int c = t + 2;
        if (c < NVCHUNK) {
            if (c >= 4) {
                const int cc = c - 4;
                mbar_wait(s0 + 8 + 8 * (cc % 3), (uint32_t)((cc / 3) & 1));
            }
            issue_chunk(c);
        }
    }

    if (wid == 0 && elect_one_pred()) tc_commit(s0 + 32);
    mbar_wait(s0 + 32, 0);
    asm volatile("tcgen05.fence::after_thread_sync;" ::: "memory");

    // Epilogue: LDTM + per-warp smem transpose + bias + scatter to Q/K/V.
    const int tile = wid >> 2;
    const int m = bm + tile * 128 + (wid & 3) * 32 + lane;
    const int b = m >> 11;
    const int nrow0 = (bm & 2047) + tile * 128 + (wid & 3) * 32;
    float* epi = (float*)(dynsmem + (s0 - sb_raw) + 1024) + wid * (32 * 33);

    for (int cb = 0; cb < 8; cb++) {
        uint32_t r[32];
        LDTM_X32(r, tmem + tile * 256 + cb * 32);
        asm volatile("tcgen05.wait::ld.sync.aligned;" ::: "memory");

        int jc = bn + cb * 32 + lane;
        float bv = bias[jc];
        int cc = jc % 3;
        int hdv = jc / 3;
        int d = hdv & 63, h = hdv >> 6;
        float* dst = (cc == 0) ? g_Q : (cc == 1) ? g_K : g_V;
        size_t colbase = ((size_t)((b << 4) + h) * SEQ) * HD + d;

        __syncwarp();
#pragma unroll
        for (int j = 0; j < 32; j++) epi[j * 33 + lane] = __uint_as_float(r[j]);
        __syncwarp();
#pragma unroll
        for (int rj = 0; rj < 32; rj++) {
            float v = epi[lane * 33 + rj] + bv;
            dst[colbase + (size_t)(nrow0 + rj) * HD] = v;
        }
        __syncwarp();
    }

    __syncthreads();
    if (wid == 0) {
        asm volatile("tcgen05.relinquish_alloc_permit.cta_group::1.sync.aligned;");
        asm volatile("tcgen05.dealloc.cta_group::1.sync.aligned.b32 %0, %1;"
                     :: "r"(tmem), "r"(512u));
    }
#else
    // -------- fallback: mma.sync quadrants, 3 accumulate passes ------------
    typedef __nv_bfloat16 RowA[128][GBK + APAD];
    RowA* As = (RowA*)dynsmem;
    RowA* Bs = (RowA*)(dynsmem + 2 * 128 * (GBK + APAD) * 2);

    const int tid = threadIdx.x;
    const int wid = tid >> 5, lane = tid & 31;
    const int wm = wid >> 2, wn = wid & 3;
    const int q = lane >> 3, rr = lane & 7;
    const int r2 = lane >> 2, c2 = lane & 3;

    const __nv_bfloat16* APASS[3] = {g_Xh, g_Xh, g_Xl};
    const __nv_bfloat16* BPASS[3] = {g_Wh, g_Wl, g_Wh};

    for (int mq = 0; mq < 2; mq++)
        for (int nq = 0; nq < 2; nq++) {
            const int bm = blockIdx.y * TBM + mq * 128;
            const int bn = blockIdx.x * TBN + nq * 128;

            float acc[4][4][4];
#pragma unroll
            for (int i = 0; i < 4; i++)
#pragma unroll
                for (int j = 0; j < 4; j++)
#pragma unroll
                    for (int k = 0; k < 4; k++) acc[i][j][k] = 0.f;

            for (int pass = 0; pass < 3; pass++) {
                const __nv_bfloat16* Ag = APASS[pass];
                const __nv_bfloat16* Bg = BPASS[pass];
                __syncthreads();

                auto issue = [&](int t, int s) {
#pragma unroll
                    for (int it = 0; it < 2; it++) {
                        int idx = tid + it * 256;
                        int row = idx >> 2, seg = (idx & 3) << 3;
                        cp16s((uint32_t)__cvta_generic_to_shared(&As[s][row][seg]),
                              &Ag[(size_t)(bm + row) * K_DIM + t * GBK + seg]);
                        cp16s((uint32_t)__cvta_generic_to_shared(&Bs[s][row][seg]),
                              &Bg[(size_t)(bn + row) * K_DIM + t * GBK + seg]);
                    }
                    asm volatile("cp.async.commit_group;" ::: "memory");
                };

                issue(0, 0);
                const int NIT = K_DIM / GBK;
                for (int t = 0; t < NIT; t++) {
                    const int buf = t & 1;
                    asm volatile("cp.async.wait_group 0;" ::: "memory");
                    __syncthreads();
                    if (t + 1 < NIT) issue(t + 1, buf ^ 1);

#pragma unroll
                    for (int ks = 0; ks < 2; ks++) {
                        uint32_t a[4][4], bb[2][4];
#pragma unroll
                        for (int mf = 0; mf < 4; mf++) {
                            int arow = wm * 64 + mf * 16 + (q & 1) * 8 + rr;
                            int acol = ks * 16 + (q >> 1) * 8;
                            ldsm_x4(a[mf], &As[buf][arow][acol]);
                        }
#pragma unroll
                        for (int nh = 0; nh < 2; nh++) {
                            int brow = wn * 32 + nh * 16 + (q >> 1) * 8 + rr;
                            int bcol = ks * 16 + (q & 1) * 8;
                            ldsm_x4(bb[nh], &Bs[buf][brow][bcol]);
                        }
#pragma unroll
                        for (int mf = 0; mf < 4; mf++)
#pragma unroll
                            for (int nf = 0; nf < 4; nf++)
                                mma_bf16(acc[mf][nf], a[mf], &bb[nf >> 1][(nf & 1) * 2]);
                    }
                    __syncthreads();
                }
            }

#pragma unroll
            for (int nf = 0; nf < 4; nf++) {
#pragma unroll
                for (int i1 = 0; i1 < 2; i1++) {
                    int jc = bn + wn * 32 + nf * 8 + c2 * 2 + i1;
                    float bv = __ldg(&bias[jc]);
                    int cc = jc % 3;
                    int hdv = jc / 3;
                    int d = hdv & 63, h = hdv >> 6;
                    float* dst = (cc == 0) ? g_Q : (cc == 1) ? g_K : g_V;
#pragma unroll
                    for (int mf = 0; mf < 4; mf++)
#pragma unroll
                        for (int i2 = 0; i2 < 2; i2++) {
                            int m = bm + wm * 64 + mf * 16 + r2 + i2 * 8;
                            int b = m >> 11, n = m & 2047;
                            dst[(((b << 4) + h) * SEQ + n) * HD + d] =
                                acc[mf][nf][i2 * 2 + i1] + bv;
                        }
                }
            }
        }
#endif
}

// ---------------------------------------------------------------------------
// Stage 2: per (bh, split): partial K^T V over a 128-row n-chunk.
// cp.async 2-stage double buffer.
// ---------------------------------------------------------------------------
__global__ __launch_bounds__(256) void ktv_partial() {
    __shared__ float Ks[2][32][64];   // 16 KB
    __shared__ float Vs[2][32][64];   // 16 KB
    const int sp = blockIdx.x, bh = blockIdx.y;
    const float* Kp = g_K + bh * SEQ * HD;
    const float* Vp = g_V + bh * SEQ * HD;
    const int tid = threadIdx.x;
    const int d1 = (tid >> 4) << 2;
    const int d2 = (tid & 15) << 2;
    float acc[4][4] = {};

    const int nbase = sp * (SEQ / NSPLIT);   // 128 rows per block

    auto load = [&](int s, int n0) {
#pragma unroll
        for (int i = 0; i < 2; i++) {
            int idx = tid + i * 256;
            int rw = idx >> 4, c4 = (idx & 15) << 2;
            cp16s((uint32_t)__cvta_generic_to_shared(&Ks[s][rw][c4]),
                  &Kp[(n0 + rw) * HD + c4]);
            cp16s((uint32_t)__cvta_generic_to_shared(&Vs[s][rw][c4]),
                  &Vp[(n0 + rw) * HD + c4]);
        }
        asm volatile("cp.async.commit_group;" ::: "memory");
    };

    load(0, nbase);
    load(1, nbase + 32);

#pragma unroll
    for (int it = 0; it < 4; it++) {
        const int buf = it & 1;
        if (it < 3)
            asm volatile("cp.async.wait_group 1;" ::: "memory");
        else
            asm volatile("cp.async.wait_group 0;" ::: "memory");
        __syncthreads();

#pragma unroll
        for (int n = 0; n < 32; n++) {
            float4 a = *(float4*)&Ks[buf][n][d1];
            float4 bq = *(float4*)&Vs[buf][n][d2];
            float av[4] = {a.x, a.y, a.z, a.w};
            float bvv[4] = {bq.x, bq.y, bq.z, bq.w};
#pragma unroll
            for (int i = 0; i < 4; i++)
#pragma unroll
                for (int j = 0; j < 4; j++)
                    acc[i][j] = fmaf(av[i], bvv[j], acc[i][j]);
        }
        __syncthreads();
        if (it + 2 < 4) load(buf, nbase + (it + 2) * 32);
    }

#pragma unroll
    for (int i = 0; i < 4; i++)
#pragma unroll
        for (int j = 0; j < 4; j++)
            g_KtVp[((bh * NSPLIT + sp) * HD + d1 + i) * HD + d2 + j] = acc[i][j];
}

// ---------------------------------------------------------------------------
// Stage 3: reduce NSPLIT partials, fold in scale = 32.
// ---------------------------------------------------------------------------
__global__ __launch_bounds__(256) void ktv_reduce() {
    int i = blockIdx.x * 256 + threadIdx.x;
    int bh = i >> 12, rc = i & 4095;
    float s = 0.f;
#pragma unroll
    for (int sp = 0; sp < NSPLIT; sp++)
        s += g_KtVp[(bh * NSPLIT + sp) * 4096 + rc];
    g_KtV[i] = 32.0f * s;
}

// ---------------------------------------------------------------------------
// Stage 4: out[bh][n][d] = Q[bh][n][:] @ KtV[bh][:][d]
// Padded smem (no bank conflicts) + float4 e-vectorized inner loop.
// ---------------------------------------------------------------------------
__global__ __launch_bounds__(256) void out_gemm(float* __restrict__ out) {
    const int bh = blockIdx.y;
    const int n0 = blockIdx.x * 64;
    __shared__ float Qs[64][68];
    __shared__ float Ms[64][68];
    const int tid = threadIdx.x;

#pragma unroll
    for (int i = 0; i < 4; i++) {
        int idx = tid + i * 256;
        int rw = idx >> 4, c4 = (idx & 15) << 2;
        *(float4*)&Ms[rw][c4] = *(const float4*)&g_KtV[(bh * HD + rw) * HD + c4];
        *(float4*)&Qs[rw][c4] = *(const float4*)&g_Q[(bh * SEQ + n0 + rw) * HD + c4];
    }
    __syncthreads();

    const int r0 = (tid >> 4) << 2;
    const int c0 = (tid & 15) << 2;
    float acc[4][4] = {};
#pragma unroll
    for (int e0 = 0; e0 < 64; e0 += 4) {
        float4 av[4], mv[4];
#pragma unroll
        for (int i = 0; i < 4; i++) av[i] = *(float4*)&Qs[r0 + i][e0];
#pragma unroll
        for (int jj = 0; jj < 4; jj++) mv[jj] = *(float4*)&Ms[e0 + jj][c0];
#pragma unroll
        for (int i = 0; i < 4; i++) {
            const float* ap = &av[i].x;
#pragma unroll
            for (int jj = 0; jj < 4; jj++) {
                const float* mp = &mv[jj].x;
#pragma unroll
                for (int j = 0; j < 4; j++)
                    acc[i][j] = fmaf(ap[jj], mp[j], acc[i][j]);
            }
        }
    }
#pragma unroll
    for (int i = 0; i < 4; i++) {
        float4 v = make_float4(acc[i][0], acc[i][1], acc[i][2], acc[i][3]);
        *(float4*)&out[(bh * SEQ + n0 + r0 + i) * HD + c0] = v;
    }
}

// ---------------------------------------------------------------------------
extern "C" void kernel_launch(void* const* d_in, const int* in_sizes, int n_in,
                              void* d_out, int out_size) {
    const float* x = (const float*)d_in[0];   // [4,2048,1024]
    const float* W = (const float*)d_in[1];   // [1024,3072]
    const float* b = (const float*)d_in[2];   // [3072]
    float* out = (float*)d_out;               // [4,16,2048,64]

    cudaFuncSetAttribute(qkv_gemm, cudaFuncAttributeMaxDynamicSharedMemorySize,
                         QKV_SMEM);

    split_x<<<(M_TOT * K_DIM) / 1024, 256>>>(x);
    split_w<<<dim3(K_DIM / 32, N_TOT / 32), 256>>>(W);
    qkv_gemm<<<dim3(N_TOT / TBN, M_TOT / TBM), 256, QKV_SMEM>>>(b);
    ktv_partial<<<dim3(NSPLIT, BH), 256>>>();
    ktv_reduce<<<(BH * HD * HD) / 256, 256>>>();
    out_gemm<<<dim3(SEQ / 64, BH), 256>>>(out);
}

// round 8
// speedup vs baseline: 1.0180x; 1.0180x over previous
#include <cuda_runtime.h>
#include <cuda_bf16.h>
#include <cstdint>

// Shapes: x [4,2048,1024] f32, W [1024,3072] f32, b [3072] f32
// out [4,16,2048,64] f32 = scale * Q (K^T V),  scale = 32
#define M_TOT 8192
#define K_DIM 1024
#define N_TOT 3072
#define BH    64
#define SEQ   2048
#define HD    64
#define NSPLIT 16

// ---- stage-1 geometry ----
#define TBM 256
#define TBN 256
#define CHUNK 64                 // bf16 k-elems per chunk = 128B rows (SW128 atom)
#define CPT 48                   // chunks per tile: 16 k-groups x 3 passes
#define NTILES 3                 // tiles per persistent CTA
#define A_TILE 32768             // 256 rows x 128B
#define B_TILE 32768
#define A_RING 3
#define B_RING 4
#define QKV_SMEM (1024 + 1024 + A_RING * A_TILE + B_RING * B_TILE)  // 231424
#define IDESC_BF16 0x08400490u   // F32 acc | aBF16 | bBF16 | N=256 | M=128

// fallback tile params
#define GBK 32
#define APAD 8

// Device-pass feature gate: tcgen05 only on arch-specific ('a') targets.
#if defined(__CUDA_ARCH__) && (defined(__CUDA_ARCH_FEAT_SM103_ALL) || \
    defined(__CUDA_ARCH_FEAT_SM100_ALL) || defined(__CUDA_ARCH_SPECIFIC__))
#define USE_TC 1
#else
#define USE_TC 0
#endif

// Scratch (device globals; no runtime allocation allowed)
__device__ __nv_bfloat16 g_Xh[(size_t)M_TOT * K_DIM];  // 16.8 MB
__device__ __nv_bfloat16 g_Xl[(size_t)M_TOT * K_DIM];  // 16.8 MB
__device__ __nv_bfloat16 g_Wh[(size_t)N_TOT * K_DIM];  // 6.3 MB (transposed)
__device__ __nv_bfloat16 g_Wl[(size_t)N_TOT * K_DIM];  // 6.3 MB
__device__ float g_Q[BH * SEQ * HD];                   // 32 MB
__device__ float g_K[BH * SEQ * HD];                   // 32 MB
__device__ float g_V[BH * SEQ * HD];                   // 32 MB
__device__ float g_KtVp[BH * NSPLIT * HD * HD];        // 16.8 MB
__device__ float g_KtV[BH * HD * HD];                  // 1 MB

// ---------------------------------------------------------------------------
// common helpers
// ---------------------------------------------------------------------------
__device__ __forceinline__ void split2(float a, float b, uint32_t& hi, uint32_t& lo) {
    __nv_bfloat16 ah = __float2bfloat16_rn(a);
    __nv_bfloat16 bh = __float2bfloat16_rn(b);
    __nv_bfloat16 al = __float2bfloat16_rn(a - __bfloat162float(ah));
    __nv_bfloat16 bl = __float2bfloat16_rn(b - __bfloat162float(bh));
    hi = (uint32_t)(*reinterpret_cast<uint16_t*>(&ah)) |
         ((uint32_t)(*reinterpret_cast<uint16_t*>(&bh)) << 16);
    lo = (uint32_t)(*reinterpret_cast<uint16_t*>(&al)) |
         ((uint32_t)(*reinterpret_cast<uint16_t*>(&bl)) << 16);
}

__device__ __forceinline__ void cp16s(uint32_t smem_addr, const void* gmem) {
    asm volatile("cp.async.cg.shared.global [%0], [%1], 16;" :: "r"(smem_addr), "l"(gmem));
}

#if USE_TC
__device__ __forceinline__ uint32_t elect_one_pred() {
    uint32_t pred;
    asm volatile("{\n\t.reg .pred p;\n\telect.sync _|p, 0xFFFFFFFF;\n\t"
                 "selp.b32 %0, 1, 0, p;\n\t}" : "=r"(pred));
    return pred;
}

static constexpr uint64_t DESC_BASE_SW128 =
    (uint64_t(2) << 61) | (uint64_t(1) << 46) | (uint64_t(64) << 32) | (uint64_t(1) << 16);
__device__ __forceinline__ uint64_t make_desc(uint32_t addr) {
    return DESC_BASE_SW128 | ((uint64_t)(addr >> 4) & 0x3FFF);
}

__device__ __forceinline__ void mma_f16_ss(uint32_t d, uint64_t ad, uint64_t bd,
                                           uint32_t idesc, uint32_t en) {
    asm volatile(
        "{\n\t.reg .pred p;\n\tsetp.ne.u32 p, %5, 0;\n\t"
        "tcgen05.mma.cta_group::1.kind::f16 [%0], %1, %2, %3, {%4,%4,%4,%4}, p;\n\t}"
        :: "r"(d), "l"(ad), "l"(bd), "r"(idesc), "r"(0u), "r"(en) : "memory");
}

__device__ __forceinline__ void mbar_init(uint32_t a, uint32_t cnt) {
    asm volatile("mbarrier.init.shared.b64 [%0], %1;" :: "r"(a), "r"(cnt) : "memory");
}
__device__ __forceinline__ void mbar_wait(uint32_t a, uint32_t parity) {
    asm volatile(
        "{\n\t.reg .pred P;\n\tLAB_%=:\n\t"
        "mbarrier.try_wait.parity.acquire.cta.shared::cta.b64 P, [%0], %1;\n\t"
        "@!P bra LAB_%=;\n\t}" :: "r"(a), "r"(parity) : "memory");
}
__device__ __forceinline__ void tc_commit(uint32_t mbar) {
    asm volatile(
        "tcgen05.commit.cta_group::1.mbarrier::arrive::one.shared::cluster.b64 [%0];"
        :: "r"(mbar) : "memory");
}

#define LDTM_X32(r, a)                                                         \
    asm volatile("tcgen05.ld.sync.aligned.32x32b.x32.b32 "                     \
        "{%0,%1,%2,%3,%4,%5,%6,%7,%8,%9,%10,%11,%12,%13,%14,%15,"              \
        "%16,%17,%18,%19,%20,%21,%22,%23,%24,%25,%26,%27,%28,%29,%30,%31},"    \
        "[%32];"                                                               \
        : "=r"((r)[0]),"=r"((r)[1]),"=r"((r)[2]),"=r"((r)[3]),                 \
          "=r"((r)[4]),"=r"((r)[5]),"=r"((r)[6]),"=r"((r)[7]),                 \
          "=r"((r)[8]),"=r"((r)[9]),"=r"((r)[10]),"=r"((r)[11]),               \
          "=r"((r)[12]),"=r"((r)[13]),"=r"((r)[14]),"=r"((r)[15]),             \
          "=r"((r)[16]),"=r"((r)[17]),"=r"((r)[18]),"=r"((r)[19]),             \
          "=r"((r)[20]),"=r"((r)[21]),"=r"((r)[22]),"=r"((r)[23]),             \
          "=r"((r)[24]),"=r"((r)[25]),"=r"((r)[26]),"=r"((r)[27]),             \
          "=r"((r)[28]),"=r"((r)[29]),"=r"((r)[30]),"=r"((r)[31])              \
        : "r"(a))
#else
__device__ __forceinline__ void mma_bf16(float* c, const uint32_t* a, const uint32_t* b) {
    asm volatile(
        "mma.sync.aligned.m16n8k16.row.col.f32.bf16.bf16.f32 "
        "{%0,%1,%2,%3}, {%4,%5,%6,%7}, {%8,%9}, {%0,%1,%2,%3};"
        : "+f"(c[0]), "+f"(c[1]), "+f"(c[2]), "+f"(c[3])
        : "r"(a[0]), "r"(a[1]), "r"(a[2]), "r"(a[3]), "r"(b[0]), "r"(b[1]));
}
__device__ __forceinline__ void ldsm_x4(uint32_t* r, const void* p) {
    uint32_t a = (uint32_t)__cvta_generic_to_shared(p);
    asm volatile("ldmatrix.sync.aligned.m8n8.x4.shared.b16 {%0,%1,%2,%3}, [%4];"
                 : "=r"(r[0]), "=r"(r[1]), "=r"(r[2]), "=r"(r[3]) : "r"(a));
}
#endif

// ---------------------------------------------------------------------------
// Precompute: x [M][K] f32 -> Xh/Xl [M][K] bf16
// ---------------------------------------------------------------------------
__global__ __launch_bounds__(256) void split_x(const float* __restrict__ x) {
    int i = blockIdx.x * 256 + threadIdx.x;
    int m = i >> 8, k4 = (i & 255) << 2;
    float4 v = *(const float4*)&x[(size_t)m * K_DIM + k4];
    uint32_t h01, l01, h23, l23;
    split2(v.x, v.y, h01, l01);
    split2(v.z, v.w, h23, l23);
    size_t base = (size_t)m * K_DIM + k4;
    *(uint2*)&g_Xh[base] = make_uint2(h01, h23);
    *(uint2*)&g_Xl[base] = make_uint2(l01, l23);
}

// ---------------------------------------------------------------------------
// Precompute: W [K][N] f32 -> Wh/Wl [N][K] bf16 (transposed)
// ---------------------------------------------------------------------------
__global__ __launch_bounds__(256) void split_w(const float* __restrict__ W) {
    __shared__ float ts[32][33];
    const int k0 = blockIdx.x * 32, n0 = blockIdx.y * 32;
    const int r = threadIdx.x >> 5, c = threadIdx.x & 31;
#pragma unroll
    for (int i = 0; i < 4; i++)
        ts[r + 8 * i][c] = W[(size_t)(k0 + r + 8 * i) * N_TOT + n0 + c];
    __syncthreads();
#pragma unroll
    for (int i = 0; i < 4; i++) {
        int n = n0 + r + 8 * i;
        float f = ts[c][r + 8 * i];
        __nv_bfloat16 hb = __float2bfloat16_rn(f);
        __nv_bfloat16 lb = __float2bfloat16_rn(f - __bfloat162float(hb));
        size_t base = (size_t)n * K_DIM + k0 + c;
        g_Wh[base] = hb;
        g_Wl[base] = lb;
    }
}

// ---------------------------------------------------------------------------
// Stage 1: persistent tcgen05 GEMM. 128 CTAs; each owns m-tile bm and 3
// consecutive n-tiles (bn0 + {0,1,2}*256). Global chunk index g = tile*48+t
// drives ring-slot mbar parity continuously across tiles. After each tile's
// MMA drain, next tile's first 2 chunks are prefetched BEFORE the epilogue so
// loads stream under LDTM+scatter. Epilogue scratch lives in ring slots A1/A2
// (never touched by that prefetch, which writes only A0/B0/B1).
// ---------------------------------------------------------------------------
extern __shared__ char dynsmem[];

__global__ __launch_bounds__(256, 1) void qkv_gemm(const float* __restrict__ bias) {
#if USE_TC
    const int tid = threadIdx.x, wid = tid >> 5, lane = tid & 31;
    const int cid = blockIdx.x;
    const int bm = (cid >> 2) * TBM;
    const int bn0 = (cid & 3) * (NTILES * TBN);

    uint32_t sb_raw = (uint32_t)__cvta_generic_to_shared(dynsmem);
    uint32_t s0 = (sb_raw + 1023) & ~1023u;
    uint32_t tilesA = s0 + 1024;
    uint32_t tilesB = tilesA + A_RING * A_TILE;

    if (tid == 0) {
        mbar_init(s0 + 8, 1);
        mbar_init(s0 + 16, 1);
        mbar_init(s0 + 24, 1);
        mbar_init(s0 + 32, 1);
    }
    if (wid == 0)
        asm volatile("tcgen05.alloc.cta_group::1.sync.aligned.shared::cta.b32 [%0], %1;"
                     :: "r"(s0), "r"(512u) : "memory");
    __syncthreads();
    uint32_t tmem;
    asm volatile("ld.shared.b32 %0, [%1];" : "=r"(tmem) : "r"(s0));

    // Load chunk by GLOBAL index g (tile = g/48, within-tile t = g%48).
    auto issue_chunk = [&](int g) {
        const int tile = g / CPT;
        const int tt = g - tile * CPT;
        const int j = tt / 3, p = tt - 3 * j;
        const int bn = bn0 + tile * TBN;
        const int ja = j * CHUNK;
        if (p != 1) {  // A load (p=0: Xh, p=2: Xl)
            const __nv_bfloat16* ag =
                ((p == 0) ? g_Xh : g_Xl) + (size_t)bm * K_DIM + ja;
            const uint32_t dst = tilesA + ((2 * j + (p == 2 ? 1 : 0)) % A_RING) * A_TILE;
#pragma unroll
            for (int i = 0; i < 8; i++) {
                int idx = tid + i * 256;
                int r = idx >> 3, s = idx & 7;
                cp16s(dst + (r << 7) + ((s ^ (r & 7)) << 4),
                      ag + (size_t)r * K_DIM + s * 8);
            }
        }
        if (p != 2) {  // B load (p=0: Wh, p=1: Wl)
            const __nv_bfloat16* bg =
                ((p == 0) ? g_Wh : g_Wl) + (size_t)bn * K_DIM + ja;
            const uint32_t dst = tilesB + ((2 * j + (p == 1 ? 1 : 0)) % B_RING) * B_TILE;
#pragma unroll
            for (int i = 0; i < 8; i++) {
                int idx = tid + i * 256;
                int r = idx >> 3, s = idx & 7;
                cp16s(dst + (r << 7) + ((s ^ (r & 7)) << 4),
                      bg + (size_t)r * K_DIM + s * 8);
            }
        }
        asm volatile("cp.async.commit_group;" ::: "memory");
    };

    issue_chunk(0);
    issue_chunk(1);

    for (int tile = 0; tile < NTILES; tile++) {
        const int gbase = tile * CPT;
        const int bn = bn0 + tile * TBN;

        // ---- mainloop: 48 chunks ----
        for (int t = 0; t < CPT; t++) {
            if (t < CPT - 1)
                asm volatile("cp.async.wait_group 1;" ::: "memory");
            else
                asm volatile("cp.async.wait_group 0;" ::: "memory");
            __syncthreads();

            if (wid == 0 && elect_one_pred()) {
                asm volatile("fence.proxy.async.shared::cta;" ::: "memory");
                const int j = t / 3, p = t - 3 * j;
                const uint32_t aslot = (2 * j + (p == 2 ? 1 : 0)) % A_RING;
                const uint32_t bslot = (2 * j + (p == 1 ? 1 : 0)) % B_RING;
                const uint32_t ab = tilesA + aslot * A_TILE;
                const uint32_t bb = tilesB + bslot * B_TILE;
                uint64_t a0 = make_desc(ab);
                uint64_t a1 = make_desc(ab + 16384);   // rows 128..255 of A tile
                uint64_t bd = make_desc(bb);
#pragma unroll
                for (int k = 0; k < 4; k++) {
                    uint32_t en = (t > 0 || k > 0) ? 1u : 0u;
                    mma_f16_ss(tmem,       a0 + k * 2, bd + k * 2, IDESC_BF16, en);
                    mma_f16_ss(tmem + 256, a1 + k * 2, bd + k * 2, IDESC_BF16, en);
                }
                tc_commit(s0 + 8 + 8 * ((gbase + t) % 3));
            }

            const int c = t + 2;
            if (c < CPT) {
                const int g = gbase + c;
                if (g >= 4) {
                    const int cc = g - 4;
                    mbar_wait(s0 + 8 + 8 * (cc % 3), (uint32_t)((cc / 3) & 1));
                }
                issue_chunk(g);
            }
        }

        // ---- drain this tile's MMAs ----
        if (wid == 0 && elect_one_pred()) tc_commit(s0 + 32);
        mbar_wait(s0 + 32, (uint32_t)(tile & 1));
        asm volatile("tcgen05.fence::after_thread_sync;" ::: "memory");

        // ---- prefetch next tile's first two chunks (overlap with epilogue) --
        if (tile + 1 < NTILES) {
            issue_chunk(gbase + CPT);
            issue_chunk(gbase + CPT + 1);
        }

        // ---- epilogue: LDTM + per-warp transpose (scratch in A1/A2) + scatter
        {
            const int half = wid >> 2;
            const int m = bm + half * 128 + (wid & 3) * 32 + lane;
            const int b = m >> 11;
            const int nrow0 = (bm & 2047) + half * 128 + (wid & 3) * 32;
            float* epi = (float*)(dynsmem + (s0 - sb_raw) + 1024 + A_TILE) +
                         wid * (32 * 33);

            for (int cb = 0; cb < 8; cb++) {
                uint32_t r[32];
                LDTM_X32(r, tmem + half * 256 + cb * 32);
                asm volatile("tcgen05.wait::ld.sync.aligned;" ::: "memory");

                int jc = bn + cb * 32 + lane;
                float bv = bias[jc];
                int cc = jc % 3;
                int hdv = jc / 3;
                int d = hdv & 63, h = hdv >> 6;
                float* dst = (cc == 0) ? g_Q : (cc == 1) ? g_K : g_V;
                size_t colbase = ((size_t)((b << 4) + h) * SEQ) * HD + d;

                __syncwarp();
#pragma unroll
                for (int j = 0; j < 32; j++) epi[j * 33 + lane] = __uint_as_float(r[j]);
                __syncwarp();
#pragma unroll
                for (int rj = 0; rj < 32; rj++) {
                    float v = epi[lane * 33 + rj] + bv;
                    dst[colbase + (size_t)(nrow0 + rj) * HD] = v;
                }
                __syncwarp();
            }
            asm volatile("tcgen05.fence::before_thread_sync;" ::: "memory");
        }
        __syncthreads();   // D fully read by all warps before next tile's en=0 MMA
    }

    if (wid == 0) {
        asm volatile("tcgen05.relinquish_alloc_permit.cta_group::1.sync.aligned;");
        asm volatile("tcgen05.dealloc.cta_group::1.sync.aligned.b32 %0, %1;"
                     :: "r"(tmem), "r"(512u));
    }
#else
    // -------- fallback: mma.sync, 3 n-tiles x quadrants, 3 accumulate passes
    typedef __nv_bfloat16 RowA[128][GBK + APAD];
    RowA* As = (RowA*)dynsmem;
    RowA* Bs = (RowA*)(dynsmem + 2 * 128 * (GBK + APAD) * 2);

    const int tid = threadIdx.x;
    const int wid = tid >> 5, lane = tid & 31;
    const int wm = wid >> 2, wn = wid & 3;
    const int q = lane >> 3, rr = lane & 7;
    const int r2 = lane >> 2, c2 = lane & 3;
    const int cid = blockIdx.x;
    const int bm_base = (cid >> 2) * TBM;
    const int bn_base = (cid & 3) * (NTILES * TBN);

    const __nv_bfloat16* APASS[3] = {g_Xh, g_Xh, g_Xl};
    const __nv_bfloat16* BPASS[3] = {g_Wh, g_Wl, g_Wh};

    for (int tile = 0; tile < NTILES; tile++)
        for (int mq = 0; mq < 2; mq++)
            for (int nq = 0; nq < 2; nq++) {
                const int bm = bm_base + mq * 128;
                const int bn = bn_base + tile * TBN + nq * 128;

                float acc[4][4][4];
#pragma unroll
                for (int i = 0; i < 4; i++)
#pragma unroll
                    for (int j = 0; j < 4; j++)
#pragma unroll
                        for (int k = 0; k < 4; k++) acc[i][j][k] = 0.f;

                for (int pass = 0; pass < 3; pass++) {
                    const __nv_bfloat16* Ag = APASS[pass];
                    const __nv_bfloat16* Bg = BPASS[pass];
                    __syncthreads();

                    auto issue = [&](int t, int s) {
#pragma unroll
                        for (int it = 0; it < 2; it++) {
                            int idx = tid + it * 256;
                            int row = idx >> 2, seg = (idx & 3) << 3;
                            cp16s((uint32_t)__cvta_generic_to_shared(&As[s][row][seg]),
                                  &Ag[(size_t)(bm + row) * K_DIM + t * GBK + seg]);
                            cp16s((uint32_t)__cvta_generic_to_shared(&Bs[s][row][seg]),
                                  &Bg[(size_t)(bn + row) * K_DIM + t * GBK + seg]);
                        }
                        asm volatile("cp.async.commit_group;" ::: "memory");
                    };

                    issue(0, 0);
                    const int NIT = K_DIM / GBK;
                    for (int t = 0; t < NIT; t++) {
                        const int buf = t & 1;
                        asm volatile("cp.async.wait_group 0;" ::: "memory");
                        __syncthreads();
                        if (t + 1 < NIT) issue(t + 1, buf ^ 1);

#pragma unroll
                        for (int ks = 0; ks < 2; ks++) {
                            uint32_t a[4][4], bb[2][4];
#pragma unroll
                            for (int mf = 0; mf < 4; mf++) {
                                int arow = wm * 64 + mf * 16 + (q & 1) * 8 + rr;
                                int acol = ks * 16 + (q >> 1) * 8;
                                ldsm_x4(a[mf], &As[buf][arow][acol]);
                            }
#pragma unroll
                            for (int nh = 0; nh < 2; nh++) {
                                int brow = wn * 32 + nh * 16 + (q >> 1) * 8 + rr;
                                int bcol = ks * 16 + (q & 1) * 8;
                                ldsm_x4(bb[nh], &Bs[buf][brow][bcol]);
                            }
#pragma unroll
                            for (int mf = 0; mf < 4; mf++)
#pragma unroll
                                for (int nf = 0; nf < 4; nf++)
                                    mma_bf16(acc[mf][nf], a[mf], &bb[nf >> 1][(nf & 1) * 2]);
                        }
                        __syncthreads();
                    }
                }

#pragma unroll
                for (int nf = 0; nf < 4; nf++) {
#pragma unroll
                    for (int i1 = 0; i1 < 2; i1++) {
                        int jc = bn + wn * 32 + nf * 8 + c2 * 2 + i1;
                        float bv = __ldg(&bias[jc]);
                        int cc = jc % 3;
                        int hdv = jc / 3;
                        int d = hdv & 63, h = hdv >> 6;
                        float* dst = (cc == 0) ? g_Q : (cc == 1) ? g_K : g_V;
#pragma unroll
                        for (int mf = 0; mf < 4; mf++)
#pragma unroll
                            for (int i2 = 0; i2 < 2; i2++) {
                                int m = bm + wm * 64 + mf * 16 + r2 + i2 * 8;
                                int b = m >> 11, n = m & 2047;
                                dst[(((b << 4) + h) * SEQ + n) * HD + d] =
                                    acc[mf][nf][i2 * 2 + i1] + bv;
                            }
                    }
                }
            }
#endif
}

// ---------------------------------------------------------------------------
// Stage 2: per (bh, split): partial K^T V over a 128-row n-chunk.
// cp.async 2-stage double buffer.
// ---------------------------------------------------------------------------
__global__ __launch_bounds__(256) void ktv_partial() {
    __shared__ float Ks[2][32][64];
    __shared__ float Vs[2][32][64];
    const int sp = blockIdx.x, bh = blockIdx.y;
    const float* Kp = g_K + bh * SEQ * HD;
    const float* Vp = g_V + bh * SEQ * HD;
    const int tid = threadIdx.x;
    const int d1 = (tid >> 4) << 2;
    const int d2 = (tid & 15) << 2;
    float acc[4][4] = {};

    const int nbase = sp * (SEQ / NSPLIT);

    auto load = [&](int s, int n0) {
#pragma unroll
        for (int i = 0; i < 2; i++) {
            int idx = tid + i * 256;
            int rw = idx >> 4, c4 = (idx & 15) << 2;
            cp16s((uint32_t)__cvta_generic_to_shared(&Ks[s][rw][c4]),
                  &Kp[(n0 + rw) * HD + c4]);
            cp16s((uint32_t)__cvta_generic_to_shared(&Vs[s][rw][c4]),
                  &Vp[(n0 + rw) * HD + c4]);
        }
        asm volatile("cp.async.commit_group;" ::: "memory");
    };

    load(0, nbase);
    load(1, nbase + 32);

#pragma unroll
    for (int it = 0; it < 4; it++) {
        const int buf = it & 1;
        if (it < 3)
            asm volatile("cp.async.wait_group 1;" ::: "memory");
        else
            asm volatile("cp.async.wait_group 0;" ::: "memory");
        __syncthreads();

#pragma unroll
        for (int n = 0; n < 32; n++) {
            float4 a = *(float4*)&Ks[buf][n][d1];
            float4 bq = *(float4*)&Vs[buf][n][d2];
            float av[4] = {a.x, a.y, a.z, a.w};
            float bvv[4] = {bq.x, bq.y, bq.z, bq.w};
#pragma unroll
            for (int i = 0; i < 4; i++)
#pragma unroll
                for (int j = 0; j < 4; j++)
                    acc[i][j] = fmaf(av[i], bvv[j], acc[i][j]);
        }
        __syncthreads();
        if (it + 2 < 4) load(buf, nbase + (it + 2) * 32);
    }

#pragma unroll
    for (int i = 0; i < 4; i++)
#pragma unroll
        for (int j = 0; j < 4; j++)
            g_KtVp[((bh * NSPLIT + sp) * HD + d1 + i) * HD + d2 + j] = acc[i][j];
}

// ---------------------------------------------------------------------------
// Stage 3: reduce NSPLIT partials, fold in scale = 32.
// ---------------------------------------------------------------------------
__global__ __launch_bounds__(256) void ktv_reduce() {
    int i = blockIdx.x * 256 + threadIdx.x;
    int bh = i >> 12, rc = i & 4095;
    float s = 0.f;
#pragma unroll
    for (int sp = 0; sp < NSPLIT; sp++)
        s += g_KtVp[(bh * NSPLIT + sp) * 4096 + rc];
    g_KtV[i] = 32.0f * s;
}

// ---------------------------------------------------------------------------
// Stage 4: out[bh][n][d] = Q[bh][n][:] @ KtV[bh][:][d]
// ---------------------------------------------------------------------------
__global__ __launch_bounds__(256) void out_gemm(float* __restrict__ out) {
    const int bh = blockIdx.y;
    const int n0 = blockIdx.x * 64;
    __shared__ float Qs[64][68];
    __shared__ float Ms[64][68];
    const int tid = threadIdx.x;

#pragma unroll
    for (int i = 0; i < 4; i++) {
        int idx = tid + i * 256;
        int rw = idx >> 4, c4 = (idx & 15) << 2;
        *(float4*)&Ms[rw][c4] = *(const float4*)&g_KtV[(bh * HD + rw) * HD + c4];
        *(float4*)&Qs[rw][c4] = *(const float4*)&g_Q[(bh * SEQ + n0 + rw) * HD + c4];
    }
    __syncthreads();

    const int r0 = (tid >> 4) << 2;
    const int c0 = (tid & 15) << 2;
    float acc[4][4] = {};
#pragma unroll
    for (int e0 = 0; e0 < 64; e0 += 4) {
        float4 av[4], mv[4];
#pragma unroll
        for (int i = 0; i < 4; i++) av[i] = *(float4*)&Qs[r0 + i][e0];
#pragma unroll
        for (int jj = 0; jj < 4; jj++) mv[jj] = *(float4*)&Ms[e0 + jj][c0];
#pragma unroll
        for (int i = 0; i < 4; i++) {
            const float* ap = &av[i].x;
#pragma unroll
            for (int jj = 0; jj < 4; jj++) {
                const float* mp = &mv[jj].x;
#pragma unroll
                for (int j = 0; j < 4; j++)
                    acc[i][j] = fmaf(ap[jj], mp[j], acc[i][j]);
            }
        }
    }
#pragma unroll
    for (int i = 0; i < 4; i++) {
        float4 v = make_float4(acc[i][0], acc[i][1], acc[i][2], acc[i][3]);
        *(float4*)&out[(bh * SEQ + n0 + r0 + i) * HD + c0] = v;
    }
}

// ---------------------------------------------------------------------------
extern "C" void kernel_launch(void* const* d_in, const int* in_sizes, int n_in,
                              void* d_out, int out_size) {
    const float* x = (const float*)d_in[0];   // [4,2048,1024]
    const float* W = (const float*)d_in[1];   // [1024,3072]
    const float* b = (const float*)d_in[2];   // [3072]
    float* out = (float*)d_out;               // [4,16,2048,64]

    cudaFuncSetAttribute(qkv_gemm, cudaFuncAttributeMaxDynamicSharedMemorySize,
                         QKV_SMEM);

    split_x<<<(M_TOT * K_DIM) / 1024, 256>>>(x);
    split_w<<<dim3(K_DIM / 32, N_TOT / 32), 256>>>(W);
    qkv_gemm<<<128, 256, QKV_SMEM>>>(b);
    ktv_partial<<<dim3(NSPLIT, BH), 256>>>();
    ktv_reduce<<<(BH * HD * HD) / 256, 256>>>();
    out_gemm<<<dim3(SEQ / 64, BH), 256>>>(out);
}